// round 1
// baseline (speedup 1.0000x reference)
#include <cuda_runtime.h>
#include <cstdint>

#define NN 50000
#define EE 800000
#define KD 128      // IN_C == HID_C
#define OC 64       // OUT_C

// ---------------- scratch (device globals; no allocation allowed) ----------
__device__ __align__(16) float g_H1[NN * KD];   // X*W1^T + b1
__device__ __align__(16) float g_A1[NN * KD];   // aggregated layer-1 (pre-relu)
__device__ __align__(16) float g_H2[NN * OC];   // relu(A1)*W2^T + b2
__device__ int   g_deg1[NN];
__device__ int   g_deg2[NN];
__device__ float g_norm1[NN];
__device__ float g_norm2[NN];

// ---------------- degree / norm kernels ------------------------------------
__global__ void k_init_deg() {
    int i = blockIdx.x * blockDim.x + threadIdx.x;
    if (i < NN) { g_deg1[i] = 1; g_deg2[i] = 1; }   // self-loop baked in
}

__global__ void k_count_deg(const int* __restrict__ ei) {
    int i = blockIdx.x * blockDim.x + threadIdx.x;
    if (i < EE) {
        int r = ei[i];
        int c = ei[EE + i];
        atomicAdd(&g_deg1[c], 1);
        atomicAdd(&g_deg2[r], 1);
    }
}

__global__ void k_norm() {
    int i = blockIdx.x * blockDim.x + threadIdx.x;
    if (i < NN) {
        g_norm1[i] = 1.0f / (float)g_deg1[i];
        g_norm2[i] = 1.0f / (float)g_deg2[i];
    }
}

// ---------------- GEMM: C[M,BN] = A[M,128] * W[BN,128]^T + bias ------------
// BM=128 rows per block, full N and K in one block. 256 threads, 8xTN per thread.
template<int BN, bool RELU_IN>
__global__ __launch_bounds__(256)
void k_gemm(const float* __restrict__ A, const float* __restrict__ W,
            const float* __restrict__ bias, float* __restrict__ C, int M) {
    constexpr int TN = BN / 16;
    __shared__ float As[32][132];
    __shared__ float Bs[32][BN + 4];

    const int tid = threadIdx.x;
    const int tx  = tid & 15;
    const int ty  = tid >> 4;
    const int m0  = blockIdx.x * 128;

    float acc[8][TN];
#pragma unroll
    for (int i = 0; i < 8; i++)
#pragma unroll
        for (int j = 0; j < TN; j++) acc[i][j] = 0.0f;

    float bj[TN];
#pragma unroll
    for (int j = 0; j < TN; j++) bj[j] = bias[tx * TN + j];

    for (int kt = 0; kt < 4; kt++) {
        const int k0 = kt * 32;
        // load A tile (128 x 32), transpose into As[k][m]
        for (int idx = tid; idx < 128 * 8; idx += 256) {
            int m = idx >> 3, f = idx & 7;
            float4 v = make_float4(0.f, 0.f, 0.f, 0.f);
            int gm = m0 + m;
            if (gm < M) v = *(const float4*)(A + (size_t)gm * KD + k0 + f * 4);
            if (RELU_IN) {
                v.x = fmaxf(v.x, 0.f); v.y = fmaxf(v.y, 0.f);
                v.z = fmaxf(v.z, 0.f); v.w = fmaxf(v.w, 0.f);
            }
            As[f * 4 + 0][m] = v.x; As[f * 4 + 1][m] = v.y;
            As[f * 4 + 2][m] = v.z; As[f * 4 + 3][m] = v.w;
        }
        // load W tile (BN x 32), transpose into Bs[k][n]
        for (int idx = tid; idx < BN * 8; idx += 256) {
            int n = idx >> 3, f = idx & 7;
            float4 v = *(const float4*)(W + (size_t)n * KD + k0 + f * 4);
            Bs[f * 4 + 0][n] = v.x; Bs[f * 4 + 1][n] = v.y;
            Bs[f * 4 + 2][n] = v.z; Bs[f * 4 + 3][n] = v.w;
        }
        __syncthreads();

#pragma unroll 8
        for (int kk = 0; kk < 32; kk++) {
            float a[8], b[TN];
            float4 t0 = *(const float4*)&As[kk][ty * 8];
            float4 t1 = *(const float4*)&As[kk][ty * 8 + 4];
            a[0] = t0.x; a[1] = t0.y; a[2] = t0.z; a[3] = t0.w;
            a[4] = t1.x; a[5] = t1.y; a[6] = t1.z; a[7] = t1.w;
            float4 u0 = *(const float4*)&Bs[kk][tx * TN];
            b[0] = u0.x; b[1] = u0.y; b[2] = u0.z; b[3] = u0.w;
            if (TN == 8) {
                float4 u1 = *(const float4*)&Bs[kk][tx * TN + 4];
                b[4] = u1.x; b[5] = u1.y; b[6] = u1.z; b[7] = u1.w;
            }
#pragma unroll
            for (int i = 0; i < 8; i++)
#pragma unroll
                for (int j = 0; j < TN; j++)
                    acc[i][j] = fmaf(a[i], b[j], acc[i][j]);
        }
        __syncthreads();
    }

#pragma unroll
    for (int i = 0; i < 8; i++) {
        int gm = m0 + ty * 8 + i;
        if (gm < M) {
#pragma unroll
            for (int j4 = 0; j4 < TN / 4; j4++) {
                float4 o;
                o.x = acc[i][j4 * 4 + 0] + bj[j4 * 4 + 0];
                o.y = acc[i][j4 * 4 + 1] + bj[j4 * 4 + 1];
                o.z = acc[i][j4 * 4 + 2] + bj[j4 * 4 + 2];
                o.w = acc[i][j4 * 4 + 3] + bj[j4 * 4 + 3];
                *(float4*)(C + (size_t)gm * BN + tx * TN + j4 * 4) = o;
            }
        }
    }
}

// ---------------- self-loop init (also zero/base-inits the accumulators) ---
__global__ void k_selfagg1() {
    int gid = blockIdx.x * blockDim.x + threadIdx.x;   // over NN*32 float4s
    if (gid < NN * 32) {
        int v = gid >> 5;
        float n = g_norm1[v];
        float4 h = ((const float4*)g_H1)[gid];
        h.x *= n; h.y *= n; h.z *= n; h.w *= n;
        ((float4*)g_A1)[gid] = h;
    }
}

__global__ void k_selfagg2(float* __restrict__ out) {
    int gid = blockIdx.x * blockDim.x + threadIdx.x;   // over NN*16 float4s
    if (gid < NN * 16) {
        int v = gid >> 4;
        float n = g_norm2[v];
        float4 h = ((const float4*)g_H2)[gid];
        h.x *= n; h.y *= n; h.z *= n; h.w *= n;
        ((float4*)out)[gid] = h;
    }
}

// ---------------- edge scatter (vector float4 reductions) -------------------
__device__ __forceinline__ void red_add_v4(float4* addr, float4 v) {
    asm volatile("red.global.add.v4.f32 [%0], {%1,%2,%3,%4};"
                 :: "l"(addr), "f"(v.x), "f"(v.y), "f"(v.z), "f"(v.w)
                 : "memory");
}

// layer 1: A1[col] += norm1[col] * H1[row], one warp per edge (128 feats)
__global__ __launch_bounds__(256)
void k_scatter1(const int* __restrict__ ei) {
    int e = blockIdx.x * 8 + (threadIdx.x >> 5);
    if (e >= EE) return;
    int lane = threadIdx.x & 31;
    int row = 0, col = 0; float n = 0.f;
    if (lane == 0) {
        row = ei[e];
        col = ei[EE + e];
        n   = g_norm1[col];
    }
    row = __shfl_sync(0xffffffffu, row, 0);
    col = __shfl_sync(0xffffffffu, col, 0);
    n   = __shfl_sync(0xffffffffu, n, 0);
    float4 v = ((const float4*)g_H1)[row * 32 + lane];
    v.x *= n; v.y *= n; v.z *= n; v.w *= n;
    red_add_v4(&((float4*)g_A1)[col * 32 + lane], v);
}

// layer 2 (flipped edges): out[row] += norm2[row] * H2[col], half warp per edge (64 feats)
__global__ __launch_bounds__(256)
void k_scatter2(const int* __restrict__ ei, float* __restrict__ out) {
    int warpg = blockIdx.x * 8 + (threadIdx.x >> 5);
    int lane  = threadIdx.x & 31;
    int e     = warpg * 2 + (lane >> 4);
    if (e >= EE) return;
    int l = lane & 15;
    int row = 0, col = 0; float n = 0.f;
    if (l == 0) {
        row = ei[e];
        col = ei[EE + e];
        n   = g_norm2[row];
    }
    int src = lane & 16;
    row = __shfl_sync(0xffffffffu, row, src);
    col = __shfl_sync(0xffffffffu, col, src);
    n   = __shfl_sync(0xffffffffu, n, src);
    float4 v = ((const float4*)g_H2)[col * 16 + l];
    v.x *= n; v.y *= n; v.z *= n; v.w *= n;
    red_add_v4(&((float4*)out)[row * 16 + l], v);
}

// ---------------- launch -----------------------------------------------------
extern "C" void kernel_launch(void* const* d_in, const int* in_sizes, int n_in,
                              void* d_out, int out_size) {
    const float* x  = (const float*)d_in[0];
    const int*   ei = (const int*)d_in[1];
    const float* W1 = (const float*)d_in[2];
    const float* b1 = (const float*)d_in[3];
    const float* W2 = (const float*)d_in[4];
    const float* b2 = (const float*)d_in[5];
    float* out = (float*)d_out;

    float *pH1, *pA1, *pH2;
    cudaGetSymbolAddress((void**)&pH1, g_H1);
    cudaGetSymbolAddress((void**)&pA1, g_A1);
    cudaGetSymbolAddress((void**)&pH2, g_H2);

    // degrees + norms
    k_init_deg<<<(NN + 255) / 256, 256>>>();
    k_count_deg<<<(EE + 255) / 256, 256>>>(ei);
    k_norm<<<(NN + 255) / 256, 256>>>();

    // layer 1
    k_gemm<128, false><<<(NN + 127) / 128, 256>>>(x, W1, b1, pH1, NN);
    k_selfagg1<<<(NN * 32 + 255) / 256, 256>>>();
    k_scatter1<<<EE / 8, 256>>>(ei);

    // layer 2 (relu folded into GEMM input read)
    k_gemm<64, true><<<(NN + 127) / 128, 256>>>(pA1, W2, b2, pH2, NN);
    k_selfagg2<<<(NN * 16 + 255) / 256, 256>>>(out);
    k_scatter2<<<EE / 2 / 8, 256>>>(ei, out);
}

// round 2
// speedup vs baseline: 1.2461x; 1.2461x over previous
#include <cuda_runtime.h>
#include <cstdint>

#define NN 50000
#define EE 800000
#define KD 128      // IN_C == HID_C
#define OC 64       // OUT_C

// ---------------- scratch (device globals; no allocation allowed) ----------
__device__ __align__(16) float g_H1[NN * KD];   // X*W1^T + b1
__device__ __align__(16) float g_A1[NN * KD];   // layer-1 aggregated (pre-relu)
__device__ __align__(16) float g_H2[NN * OC];   // relu(A1)*W2^T + b2
__device__ int   g_deg1[NN], g_deg2[NN];
__device__ int   g_off1[NN], g_off2[NN];
__device__ int   g_cur1[NN], g_cur2[NN];
__device__ int   g_csr1[EE], g_csr2[EE];
__device__ float g_norm1[NN], g_norm2[NN];
__device__ int   g_tot1, g_tot2;

// ---------------- f32x2 helpers (Blackwell packed fp32) ---------------------
__device__ __forceinline__ unsigned long long pk2(float lo, float hi) {
    unsigned long long r;
    asm("mov.b64 %0, {%1, %2};" : "=l"(r) : "f"(lo), "f"(hi));
    return r;
}
__device__ __forceinline__ void up2(unsigned long long v, float& lo, float& hi) {
    asm("mov.b64 {%0, %1}, %2;" : "=f"(lo), "=f"(hi) : "l"(v));
}
__device__ __forceinline__ void ffma2(unsigned long long& d,
                                      unsigned long long a, unsigned long long b) {
    asm("fma.rn.f32x2 %0, %1, %2, %0;" : "+l"(d) : "l"(a), "l"(b));
}

// ---------------- init / degree / offsets / fill ----------------------------
__global__ void k_init() {
    int i = blockIdx.x * blockDim.x + threadIdx.x;
    if (i < NN) { g_deg1[i] = 0; g_deg2[i] = 0; }
    if (i == 0) { g_tot1 = 0; g_tot2 = 0; }
}

__global__ void k_count(const int* __restrict__ ei) {
    int e = blockIdx.x * blockDim.x + threadIdx.x;
    if (e < EE) {
        atomicAdd(&g_deg1[ei[EE + e]], 1);   // in-degree (dest = col)
        atomicAdd(&g_deg2[ei[e]], 1);        // flipped in-degree (dest = row)
    }
}

// block-wide exclusive scan of degrees -> CSR offsets + cursors + norms
__global__ __launch_bounds__(256) void k_offsets() {
    int v = blockIdx.x * 256 + threadIdx.x;
    int lane = threadIdx.x & 31, w = threadIdx.x >> 5;
    int d1 = (v < NN) ? g_deg1[v] : 0;
    int d2 = (v < NN) ? g_deg2[v] : 0;
    int x1 = d1, x2 = d2;
#pragma unroll
    for (int o = 1; o < 32; o <<= 1) {
        int y1 = __shfl_up_sync(0xffffffffu, x1, o);
        int y2 = __shfl_up_sync(0xffffffffu, x2, o);
        if (lane >= o) { x1 += y1; x2 += y2; }
    }
    __shared__ int ws1[8], ws2[8], sbase[2];
    if (lane == 31) { ws1[w] = x1; ws2[w] = x2; }
    __syncthreads();
    int pre1 = 0, tot1 = 0, pre2 = 0, tot2 = 0;
#pragma unroll
    for (int i = 0; i < 8; i++) {
        int a = ws1[i], b = ws2[i];
        if (i < w) { pre1 += a; pre2 += b; }
        tot1 += a; tot2 += b;
    }
    if (threadIdx.x == 0) {
        sbase[0] = atomicAdd(&g_tot1, tot1);
        sbase[1] = atomicAdd(&g_tot2, tot2);
    }
    __syncthreads();
    if (v < NN) {
        int o1 = sbase[0] + pre1 + (x1 - d1);
        int o2 = sbase[1] + pre2 + (x2 - d2);
        g_off1[v] = o1; g_cur1[v] = o1;
        g_off2[v] = o2; g_cur2[v] = o2;
        g_norm1[v] = 1.0f / (float)(d1 + 1);   // +1 self loop
        g_norm2[v] = 1.0f / (float)(d2 + 1);
    }
}

__global__ void k_fill(const int* __restrict__ ei) {
    int e = blockIdx.x * blockDim.x + threadIdx.x;
    if (e < EE) {
        int r = ei[e], c = ei[EE + e];
        int p1 = atomicAdd(&g_cur1[c], 1);
        g_csr1[p1] = r;                       // layer1: dest=col gathers row
        int p2 = atomicAdd(&g_cur2[r], 1);
        g_csr2[p2] = c;                       // layer2 (flipped): dest=row gathers col
    }
}

// ---------------- GEMM: C[M,BN] = A[M,128]*W[BN,128]^T + bias  (f32x2) ------
// 128-row tile, full K=128 in smem, single __syncthreads.
// As row-major [m][k] (stride-1 STS, broadcast scalar LDS).
// Bs k-major [k][n] (per-lane-row W loads -> stride-1 STS; W is L2-resident).
template<int BN, bool RELU>
__global__ __launch_bounds__(256, 1)
void k_gemm(const float* __restrict__ A, const float* __restrict__ W,
            const float* __restrict__ bias, float* __restrict__ C, int M) {
    constexpr int TN = BN / 16;
    extern __shared__ float sm[];
    float* As = sm;              // 128*128
    float* Bs = sm + 128 * 128;  // 128*BN
    const int tid = threadIdx.x;
    const int tx = tid & 15, ty = tid >> 4;
    const int m0 = blockIdx.x * 128;

    // A tile: warp reads one row per iter (coalesced 512B), STS.128 stride-1
    for (int idx = tid; idx < 128 * 32; idx += 256) {
        int m = idx >> 5, f = idx & 31;
        float4 v = make_float4(0.f, 0.f, 0.f, 0.f);
        int gm = m0 + m;
        if (gm < M) v = *(const float4*)(A + (size_t)gm * KD + f * 4);
        if (RELU) {
            v.x = fmaxf(v.x, 0.f); v.y = fmaxf(v.y, 0.f);
            v.z = fmaxf(v.z, 0.f); v.w = fmaxf(v.w, 0.f);
        }
        *(float4*)(As + m * 128 + f * 4) = v;
    }
    // B tile: lane n = idx&(BN-1), f = idx>>log2(BN); scalar STS stride-1 in n
    for (int idx = tid; idx < BN * 32; idx += 256) {
        int n = idx & (BN - 1);
        int f = idx / BN;
        float4 v = *(const float4*)(W + (size_t)n * KD + f * 4);
        Bs[(f * 4 + 0) * BN + n] = v.x;
        Bs[(f * 4 + 1) * BN + n] = v.y;
        Bs[(f * 4 + 2) * BN + n] = v.z;
        Bs[(f * 4 + 3) * BN + n] = v.w;
    }
    __syncthreads();

    unsigned long long acc[4][TN];
#pragma unroll
    for (int i = 0; i < 4; i++)
#pragma unroll
        for (int j = 0; j < TN; j++) acc[i][j] = 0ULL;

#pragma unroll 4
    for (int kk = 0; kk < 128; kk++) {
        const float* ar = As + (ty * 8) * 128 + kk;
        unsigned long long ap[4];
#pragma unroll
        for (int i = 0; i < 4; i++)
            ap[i] = pk2(ar[(2 * i) * 128], ar[(2 * i + 1) * 128]);
        unsigned long long bd[TN];
        {
            float4 b0 = *(const float4*)(Bs + kk * BN + tx * TN);
            bd[0] = pk2(b0.x, b0.x); bd[1] = pk2(b0.y, b0.y);
            bd[2] = pk2(b0.z, b0.z); bd[3] = pk2(b0.w, b0.w);
            if (TN == 8) {
                float4 b1 = *(const float4*)(Bs + kk * BN + tx * TN + 4);
                bd[4] = pk2(b1.x, b1.x); bd[5] = pk2(b1.y, b1.y);
                bd[6] = pk2(b1.z, b1.z); bd[7] = pk2(b1.w, b1.w);
            }
        }
#pragma unroll
        for (int i = 0; i < 4; i++)
#pragma unroll
            for (int j = 0; j < TN; j++)
                ffma2(acc[i][j], ap[i], bd[j]);
    }

    float bj[TN];
#pragma unroll
    for (int j = 0; j < TN; j++) bj[j] = bias[tx * TN + j];

#pragma unroll
    for (int mp = 0; mp < 4; mp++) {
        float lo[TN], hi[TN];
#pragma unroll
        for (int j = 0; j < TN; j++) up2(acc[mp][j], lo[j], hi[j]);
        int r0 = m0 + ty * 8 + mp * 2;
        if (r0 < M) {
#pragma unroll
            for (int q = 0; q < TN / 4; q++) {
                float4 o;
                o.x = lo[q * 4 + 0] + bj[q * 4 + 0];
                o.y = lo[q * 4 + 1] + bj[q * 4 + 1];
                o.z = lo[q * 4 + 2] + bj[q * 4 + 2];
                o.w = lo[q * 4 + 3] + bj[q * 4 + 3];
                *(float4*)(C + (size_t)r0 * BN + tx * TN + q * 4) = o;
            }
        }
        if (r0 + 1 < M) {
#pragma unroll
            for (int q = 0; q < TN / 4; q++) {
                float4 o;
                o.x = hi[q * 4 + 0] + bj[q * 4 + 0];
                o.y = hi[q * 4 + 1] + bj[q * 4 + 1];
                o.z = hi[q * 4 + 2] + bj[q * 4 + 2];
                o.w = hi[q * 4 + 3] + bj[q * 4 + 3];
                *(float4*)(C + (size_t)(r0 + 1) * BN + tx * TN + q * 4) = o;
            }
        }
    }
}

// ---------------- CSR gather (warp per node) --------------------------------
// A1[v] = norm1[v] * (H1[v] + sum_{u in N(v)} H1[u]),  128 feats = 32 x float4
__global__ __launch_bounds__(256) void k_gather1() {
    int v = blockIdx.x * 8 + (threadIdx.x >> 5);
    if (v >= NN) return;
    int lane = threadIdx.x & 31;
    const float4* H = (const float4*)g_H1;
    int deg = g_deg1[v];
    const int* __restrict__ src = g_csr1 + g_off1[v];
    float4 a0 = H[(size_t)v * 32 + lane];
    float4 a1 = make_float4(0.f, 0.f, 0.f, 0.f);
    int j = 0;
    while (j < deg) {
        int cnt = deg - j; if (cnt > 32) cnt = 32;
        int u = (lane < cnt) ? src[j + lane] : 0;
        int k = 0;
        for (; k + 2 <= cnt; k += 2) {
            int u0 = __shfl_sync(0xffffffffu, u, k);
            int u1 = __shfl_sync(0xffffffffu, u, k + 1);
            float4 x0 = H[(size_t)u0 * 32 + lane];
            float4 x1 = H[(size_t)u1 * 32 + lane];
            a0.x += x0.x; a0.y += x0.y; a0.z += x0.z; a0.w += x0.w;
            a1.x += x1.x; a1.y += x1.y; a1.z += x1.z; a1.w += x1.w;
        }
        if (k < cnt) {
            int u0 = __shfl_sync(0xffffffffu, u, k);
            float4 x0 = H[(size_t)u0 * 32 + lane];
            a0.x += x0.x; a0.y += x0.y; a0.z += x0.z; a0.w += x0.w;
        }
        j += cnt;
    }
    float n = g_norm1[v];
    float4 o;
    o.x = n * (a0.x + a1.x); o.y = n * (a0.y + a1.y);
    o.z = n * (a0.z + a1.z); o.w = n * (a0.w + a1.w);
    ((float4*)g_A1)[(size_t)v * 32 + lane] = o;
}

// out[v] = norm2[v] * (H2[v] + sum H2[u]),  64 feats = 32 x float2
__global__ __launch_bounds__(256) void k_gather2(float* __restrict__ out) {
    int v = blockIdx.x * 8 + (threadIdx.x >> 5);
    if (v >= NN) return;
    int lane = threadIdx.x & 31;
    const float2* H = (const float2*)g_H2;
    int deg = g_deg2[v];
    const int* __restrict__ src = g_csr2 + g_off2[v];
    float2 a0 = H[(size_t)v * 32 + lane];
    float2 a1 = make_float2(0.f, 0.f);
    int j = 0;
    while (j < deg) {
        int cnt = deg - j; if (cnt > 32) cnt = 32;
        int u = (lane < cnt) ? src[j + lane] : 0;
        int k = 0;
        for (; k + 2 <= cnt; k += 2) {
            int u0 = __shfl_sync(0xffffffffu, u, k);
            int u1 = __shfl_sync(0xffffffffu, u, k + 1);
            float2 x0 = H[(size_t)u0 * 32 + lane];
            float2 x1 = H[(size_t)u1 * 32 + lane];
            a0.x += x0.x; a0.y += x0.y;
            a1.x += x1.x; a1.y += x1.y;
        }
        if (k < cnt) {
            int u0 = __shfl_sync(0xffffffffu, u, k);
            float2 x0 = H[(size_t)u0 * 32 + lane];
            a0.x += x0.x; a0.y += x0.y;
        }
        j += cnt;
    }
    float n = g_norm2[v];
    float2 o;
    o.x = n * (a0.x + a1.x); o.y = n * (a0.y + a1.y);
    ((float2*)out)[(size_t)v * 32 + lane] = o;
}

// ---------------- launch -----------------------------------------------------
extern "C" void kernel_launch(void* const* d_in, const int* in_sizes, int n_in,
                              void* d_out, int out_size) {
    const float* x  = (const float*)d_in[0];
    const int*   ei = (const int*)d_in[1];
    const float* W1 = (const float*)d_in[2];
    const float* b1 = (const float*)d_in[3];
    const float* W2 = (const float*)d_in[4];
    const float* b2 = (const float*)d_in[5];
    float* out = (float*)d_out;

    float *pH1, *pA1, *pH2;
    cudaGetSymbolAddress((void**)&pH1, g_H1);
    cudaGetSymbolAddress((void**)&pA1, g_A1);
    cudaGetSymbolAddress((void**)&pH2, g_H2);

    cudaFuncSetAttribute(k_gemm<128, false>,
                         cudaFuncAttributeMaxDynamicSharedMemorySize, 131072);
    cudaFuncSetAttribute(k_gemm<64, true>,
                         cudaFuncAttributeMaxDynamicSharedMemorySize, 98304);

    // graph preprocessing
    k_init<<<(NN + 255) / 256, 256>>>();
    k_count<<<(EE + 255) / 256, 256>>>(ei);
    k_offsets<<<(NN + 255) / 256, 256>>>();
    k_fill<<<(EE + 255) / 256, 256>>>(ei);

    // layer 1
    k_gemm<128, false><<<(NN + 127) / 128, 256, 131072>>>(x, W1, b1, pH1, NN);
    k_gather1<<<NN / 8, 256>>>();

    // layer 2 (relu folded into GEMM input read)
    k_gemm<64, true><<<(NN + 127) / 128, 256, 98304>>>(pA1, W2, b2, pH2, NN);
    k_gather2<<<NN / 8, 256>>>(out);
}